// round 12
// baseline (speedup 1.0000x reference)
#include <cuda_runtime.h>
#include <cuda_fp16.h>

// Round 12: chunked K1/K2 software pipeline on two streams (graph fork/join).
// K1 (l1tex-bound, DRAM 7%) and K2 (DRAM-bound 63%) use complementary
// resources; serially they cost 66+28.6us. Points split into 4 groups:
// K1(g) on stream0 (144 blocks = 1 clean wave), K2(g) on stream s2 after an
// event on K1(g). K2's small blocks (512thr/33KB) drain into SM gaps while
// K1(g+1) runs. Kernel bodies identical to R11 (proven 94.7us).

#define NLV 16
#define TBL 16384
#define BT  1024
#define GROUPS 4
#define CPG 18                 // chunks per group: 8*18 = 144 blocks/group
#define NCHUNK (GROUPS * CPG)  // 72
#define MAXB 1048576
#define SC   8192.0f
#define SCI  (1.0f / 8192.0f)

__device__ __half2 g_scr[NLV * MAXB];   // 64 MB, layout (level, point)

__constant__ int c_res[NLV]  = {16, 20, 25, 32, 40, 50, 64, 80,
                                101, 128, 161, 203, 256, 322, 406, 512};
__constant__ int c_nenc[NLV] = {4096, 8000, 15625, 16384, 16384, 16384, 16384, 16384,
                                16384, 16384, 16384, 16384, 16384, 16384, 16384, 16384};

__device__ __forceinline__ void level_compute(
    float px, float py, float pz, int res, int nenc, bool hashing,
    const __half2* __restrict__ tab, __half2* __restrict__ scr, int b)
{
    const float resf = (float)res;
    const float sx = (px + 1.0f) * resf * 0.5f - 0.5f;
    const float sy = (py + 1.0f) * resf * 0.5f - 0.5f;
    const float sz = (pz + 1.0f) * resf * 0.5f - 0.5f;
    const float flx = floorf(sx), fly = floorf(sy), flz = floorf(sz);
    const float fx = sx - flx, fy = sy - fly, fz = sz - flz;
    const int cx = (int)flx, cy = (int)fly, cz = (int)flz;

    const float wx0 = (cx >= 0)       ? 1.0f - fx : 0.0f;
    const float wx1 = (cx <  res - 1) ? fx        : 0.0f;
    const float wy0 = (cy >= 0)       ? 1.0f - fy : 0.0f;
    const float wy1 = (cy <  res - 1) ? fy        : 0.0f;
    const float wz0 = (cz >= 0)       ? 1.0f - fz : 0.0f;
    const float wz1 = (cz <  res - 1) ? fz        : 0.0f;

    const float w00 = wx0 * wy0, w01 = wx0 * wy1;
    const float w10 = wx1 * wy0, w11 = wx1 * wy1;

    unsigned id[8];
    if (hashing) {
        const unsigned hx0 = (unsigned)cx;
        const unsigned hx1 = (unsigned)(cx + 1);
        const unsigned hy0 = (unsigned)cy       * 2654435761u;
        const unsigned hy1 = (unsigned)(cy + 1) * 2654435761u;
        const unsigned hz0 = (unsigned)cz       * 805459861u;
        const unsigned hz1 = (unsigned)(cz + 1) * 805459861u;
        const unsigned g00 = hx0 ^ hy0, g01 = hx0 ^ hy1;
        const unsigned g10 = hx1 ^ hy0, g11 = hx1 ^ hy1;
        const unsigned m = (unsigned)(nenc - 1);
        id[0] = (g00 ^ hz0) & m;  id[1] = (g00 ^ hz1) & m;
        id[2] = (g01 ^ hz0) & m;  id[3] = (g01 ^ hz1) & m;
        id[4] = (g10 ^ hz0) & m;  id[5] = (g10 ^ hz1) & m;
        id[6] = (g11 ^ hz0) & m;  id[7] = (g11 ^ hz1) & m;
    } else {
        const int r2 = res * res;
        const int a0 = cx,        a1 = cx + 1;
        const int b0v = cy * res, b1v = (cy + 1) * res;
        const int c0v = cz * r2,  c1v = (cz + 1) * r2;
        const unsigned lim = (unsigned)(nenc - 1);
        id[0] = min((unsigned)(a0 + b0v + c0v), lim);
        id[1] = min((unsigned)(a0 + b0v + c1v), lim);
        id[2] = min((unsigned)(a0 + b1v + c0v), lim);
        id[3] = min((unsigned)(a0 + b1v + c1v), lim);
        id[4] = min((unsigned)(a1 + b0v + c0v), lim);
        id[5] = min((unsigned)(a1 + b0v + c1v), lim);
        id[6] = min((unsigned)(a1 + b1v + c0v), lim);
        id[7] = min((unsigned)(a1 + b1v + c1v), lim);
    }

    const float w[8] = { w00 * wz0, w00 * wz1, w01 * wz0, w01 * wz1,
                         w10 * wz0, w10 * wz1, w11 * wz0, w11 * wz1 };

    float ax = 0.0f, ay = 0.0f;
    #pragma unroll
    for (int k = 0; k < 8; k++) {
        const float2 e = __half22float2(tab[id[k]]);
        ax = fmaf(w[k], e.x, ax);
        ay = fmaf(w[k], e.y, ay);
    }

    scr[b] = __floats2half2_rn(ax, ay);
}

__global__ __launch_bounds__(BT, 1)
void hashenc_kernel(const float* __restrict__ x,
                    const float* __restrict__ emb,
                    int npts, int ppb, int chunk0)
{
    const int pair = blockIdx.x;
    const int lA = 2 * pair, lB = 2 * pair + 1;
    const int resA = c_res[lA],  resB = c_res[lB];
    const int neA  = c_nenc[lA], neB  = c_nenc[lB];
    const bool hA = (lA >= 3), hB = (lB >= 3);

    extern __shared__ __half2 tab[];
    __half2* tabA = tab;
    __half2* tabB = tab + TBL;
    {
        const float2* srcA = reinterpret_cast<const float2*>(emb) + lA * TBL;
        const float2* srcB = reinterpret_cast<const float2*>(emb) + lB * TBL;
        for (int i = threadIdx.x; i < neA; i += BT) {
            const float2 v = __ldg(srcA + i);
            tabA[i] = __floats2half2_rn(v.x * SC, v.y * SC);
        }
        for (int i = threadIdx.x; i < neB; i += BT) {
            const float2 v = __ldg(srcB + i);
            tabB[i] = __floats2half2_rn(v.x * SC, v.y * SC);
        }
    }
    __syncthreads();

    const int b0 = (chunk0 + blockIdx.y) * ppb;
    const int b1 = min(npts, b0 + ppb);
    __half2* scrA = g_scr + (size_t)lA * npts;
    __half2* scrB = g_scr + (size_t)lB * npts;

    for (int b = b0 + (int)threadIdx.x; b < b1; b += BT) {
        const float px = x[3 * b + 0];
        const float py = x[3 * b + 1];
        const float pz = x[3 * b + 2];
        level_compute(px, py, pz, resA, neA, hA, tabA, scrA, b);
        level_compute(px, py, pz, resB, neB, hB, tabB, scrB, b);
    }
}

// (L,B) half2 -> (B,16,2) fp32 for points [p0, ...). Tile 512 pts, 512 thr.
#define TPP 512
#define KT  512
#define TSTR 514

__global__ __launch_bounds__(KT)
void transpose_kernel(float4* __restrict__ out, int npts, int p0)
{
    __shared__ __half2 tile[NLV * TSTR];

    const int b0 = p0 + blockIdx.x * TPP;
    const int t  = threadIdx.x;
    if (b0 >= npts) return;
    const bool full = (b0 + TPP <= npts);
    const bool vec  = full && ((npts & 3) == 0);   // uint4 path needs 16B align

    if (vec) {
        #pragma unroll
        for (int idx = t; idx < NLV * (TPP / 4); idx += KT) {
            const int l = idx >> 7;
            const int j = idx & 127;
            const uint4 v = __ldcs(reinterpret_cast<const uint4*>(
                &g_scr[(size_t)l * npts + b0 + 4 * j]));
            uint2* dst = reinterpret_cast<uint2*>(&tile[l * TSTR + 4 * j]);
            dst[0] = make_uint2(v.x, v.y);
            dst[1] = make_uint2(v.z, v.w);
        }
    } else {
        for (int idx = t; idx < NLV * TPP; idx += KT) {
            const int l = idx >> 9;
            const int p = idx & (TPP - 1);
            tile[l * TSTR + p] = (b0 + p < npts)
                ? g_scr[(size_t)l * npts + b0 + p]
                : __floats2half2_rn(0.f, 0.f);
        }
    }
    __syncthreads();

    float4* obase = out + (size_t)b0 * 8;
    #pragma unroll
    for (int i = t; i < TPP * 8; i += KT) {
        const int p  = i >> 3;
        const int jp = i & 7;
        if (full || b0 + p < npts) {
            const float2 e0 = __half22float2(tile[(2 * jp)     * TSTR + p]);
            const float2 e1 = __half22float2(tile[(2 * jp + 1) * TSTR + p]);
            __stcs(&obase[i],
                   make_float4(e0.x * SCI, e0.y * SCI, e1.x * SCI, e1.y * SCI));
        }
    }
}

extern "C" void kernel_launch(void* const* d_in, const int* in_sizes, int n_in,
                              void* d_out, int out_size)
{
    const float* x   = (const float*)d_in[0];   // (B, 3) float32
    const float* emb = (const float*)d_in[1];   // (16, 16384, 2) float32
    float4* out      = (float4*)d_out;          // (B, 16, 2) float32

    const int npts = in_sizes[0] / 3;
    // chunk size: ceil over 72 chunks, rounded up to 512 for K2 tile alignment
    int ppb = (npts + NCHUNK - 1) / NCHUNK;
    ppb = (ppb + TPP - 1) / TPP * TPP;
    const int smem = 2 * TBL * (int)sizeof(__half2); // 128 KB

    // lazy one-time creation of the second stream + events (no device memory)
    static cudaStream_t s2 = nullptr;
    static cudaEvent_t evK1[GROUPS];
    static cudaEvent_t evDone = nullptr;
    if (!s2) {
        cudaStreamCreateWithFlags(&s2, cudaStreamNonBlocking);
        for (int g = 0; g < GROUPS; g++)
            cudaEventCreateWithFlags(&evK1[g], cudaEventDisableTiming);
        cudaEventCreateWithFlags(&evDone, cudaEventDisableTiming);
        cudaFuncSetAttribute(hashenc_kernel,
                             cudaFuncAttributeMaxDynamicSharedMemorySize, smem);
    }

    for (int g = 0; g < GROUPS; g++) {
        hashenc_kernel<<<dim3(NLV / 2, CPG), BT, smem>>>(
            x, emb, npts, ppb, g * CPG);
        cudaEventRecord(evK1[g], 0);
        cudaStreamWaitEvent(s2, evK1[g], 0);

        const int p0  = g * CPG * ppb;
        const int pts = min(npts - p0, CPG * ppb);
        if (pts > 0) {
            const int tiles = (pts + TPP - 1) / TPP;
            transpose_kernel<<<tiles, KT, 0, s2>>>(out, npts, p0);
        }
    }
    cudaEventRecord(evDone, s2);
    cudaStreamWaitEvent(0, evDone, 0);
}

// round 13
// speedup vs baseline: 1.1405x; 1.1405x over previous
#include <cuda_runtime.h>
#include <cuda_fp16.h>

// Round 13: K1/K2 overlap retry with co-residency actually satisfied.
// R12 failed serially because K1 (48K regs) + K2 (16K regs) = the whole 64K
// register file -> K2 could never nest beside K1. Fix: K2 = 256 thr,
// launch_bounds(256,8) (<=32 regs = 8K/block), 16.6KB smem -> 2 K2 blocks fit
// in each SM's leftover (1024 thr, 16K regs, 100KB smem). 2 groups only:
// K1(g) = 144 blocks = 1 clean wave; K2(g0) overlaps K1(g1).

#define NLV 16
#define TBL 16384
#define BT  1024
#define GROUPS 2
#define CPG 18
#define NCHUNK (GROUPS * CPG)   // 36
#define MAXB 1048576
#define SC   8192.0f
#define SCI  (1.0f / 8192.0f)

__device__ __half2 g_scr[NLV * MAXB];   // 64 MB, layout (level, point)

__constant__ int c_res[NLV]  = {16, 20, 25, 32, 40, 50, 64, 80,
                                101, 128, 161, 203, 256, 322, 406, 512};
__constant__ int c_nenc[NLV] = {4096, 8000, 15625, 16384, 16384, 16384, 16384, 16384,
                                16384, 16384, 16384, 16384, 16384, 16384, 16384, 16384};

__device__ __forceinline__ void level_compute(
    float px, float py, float pz, int res, int nenc, bool hashing,
    const __half2* __restrict__ tab, __half2* __restrict__ scr, int b)
{
    const float resf = (float)res;
    const float sx = (px + 1.0f) * resf * 0.5f - 0.5f;
    const float sy = (py + 1.0f) * resf * 0.5f - 0.5f;
    const float sz = (pz + 1.0f) * resf * 0.5f - 0.5f;
    const float flx = floorf(sx), fly = floorf(sy), flz = floorf(sz);
    const float fx = sx - flx, fy = sy - fly, fz = sz - flz;
    const int cx = (int)flx, cy = (int)fly, cz = (int)flz;

    const float wx0 = (cx >= 0)       ? 1.0f - fx : 0.0f;
    const float wx1 = (cx <  res - 1) ? fx        : 0.0f;
    const float wy0 = (cy >= 0)       ? 1.0f - fy : 0.0f;
    const float wy1 = (cy <  res - 1) ? fy        : 0.0f;
    const float wz0 = (cz >= 0)       ? 1.0f - fz : 0.0f;
    const float wz1 = (cz <  res - 1) ? fz        : 0.0f;

    const float w00 = wx0 * wy0, w01 = wx0 * wy1;
    const float w10 = wx1 * wy0, w11 = wx1 * wy1;

    unsigned id[8];
    if (hashing) {
        const unsigned hx0 = (unsigned)cx;
        const unsigned hx1 = (unsigned)(cx + 1);
        const unsigned hy0 = (unsigned)cy       * 2654435761u;
        const unsigned hy1 = (unsigned)(cy + 1) * 2654435761u;
        const unsigned hz0 = (unsigned)cz       * 805459861u;
        const unsigned hz1 = (unsigned)(cz + 1) * 805459861u;
        const unsigned g00 = hx0 ^ hy0, g01 = hx0 ^ hy1;
        const unsigned g10 = hx1 ^ hy0, g11 = hx1 ^ hy1;
        const unsigned m = (unsigned)(nenc - 1);
        id[0] = (g00 ^ hz0) & m;  id[1] = (g00 ^ hz1) & m;
        id[2] = (g01 ^ hz0) & m;  id[3] = (g01 ^ hz1) & m;
        id[4] = (g10 ^ hz0) & m;  id[5] = (g10 ^ hz1) & m;
        id[6] = (g11 ^ hz0) & m;  id[7] = (g11 ^ hz1) & m;
    } else {
        const int r2 = res * res;
        const int a0 = cx,        a1 = cx + 1;
        const int b0v = cy * res, b1v = (cy + 1) * res;
        const int c0v = cz * r2,  c1v = (cz + 1) * r2;
        const unsigned lim = (unsigned)(nenc - 1);
        id[0] = min((unsigned)(a0 + b0v + c0v), lim);
        id[1] = min((unsigned)(a0 + b0v + c1v), lim);
        id[2] = min((unsigned)(a0 + b1v + c0v), lim);
        id[3] = min((unsigned)(a0 + b1v + c1v), lim);
        id[4] = min((unsigned)(a1 + b0v + c0v), lim);
        id[5] = min((unsigned)(a1 + b0v + c1v), lim);
        id[6] = min((unsigned)(a1 + b1v + c0v), lim);
        id[7] = min((unsigned)(a1 + b1v + c1v), lim);
    }

    const float w[8] = { w00 * wz0, w00 * wz1, w01 * wz0, w01 * wz1,
                         w10 * wz0, w10 * wz1, w11 * wz0, w11 * wz1 };

    float ax = 0.0f, ay = 0.0f;
    #pragma unroll
    for (int k = 0; k < 8; k++) {
        const float2 e = __half22float2(tab[id[k]]);
        ax = fmaf(w[k], e.x, ax);
        ay = fmaf(w[k], e.y, ay);
    }

    scr[b] = __floats2half2_rn(ax, ay);
}

__global__ __launch_bounds__(BT, 1)
void hashenc_kernel(const float* __restrict__ x,
                    const float* __restrict__ emb,
                    int npts, int ppb, int chunk0)
{
    const int pair = blockIdx.x;
    const int lA = 2 * pair, lB = 2 * pair + 1;
    const int resA = c_res[lA],  resB = c_res[lB];
    const int neA  = c_nenc[lA], neB  = c_nenc[lB];
    const bool hA = (lA >= 3), hB = (lB >= 3);

    extern __shared__ __half2 tab[];
    __half2* tabA = tab;
    __half2* tabB = tab + TBL;
    {
        const float2* srcA = reinterpret_cast<const float2*>(emb) + lA * TBL;
        const float2* srcB = reinterpret_cast<const float2*>(emb) + lB * TBL;
        for (int i = threadIdx.x; i < neA; i += BT) {
            const float2 v = __ldg(srcA + i);
            tabA[i] = __floats2half2_rn(v.x * SC, v.y * SC);
        }
        for (int i = threadIdx.x; i < neB; i += BT) {
            const float2 v = __ldg(srcB + i);
            tabB[i] = __floats2half2_rn(v.x * SC, v.y * SC);
        }
    }
    __syncthreads();

    const int b0 = (chunk0 + blockIdx.y) * ppb;
    const int b1 = min(npts, b0 + ppb);
    __half2* scrA = g_scr + (size_t)lA * npts;
    __half2* scrB = g_scr + (size_t)lB * npts;

    for (int b = b0 + (int)threadIdx.x; b < b1; b += BT) {
        const float px = x[3 * b + 0];
        const float py = x[3 * b + 1];
        const float pz = x[3 * b + 2];
        level_compute(px, py, pz, resA, neA, hA, tabA, scrA, b);
        level_compute(px, py, pz, resB, neB, hB, tabB, scrB, b);
    }
}

// (L,B) half2 -> (B,16,2) fp32. Small blocks so they nest beside K1:
// 256 thr, <=32 regs (8K/block), ~16.6KB smem.
#define TPP 256
#define KT  256
#define TSTR 258   // 258 mod 32 = 2: phase2 reads hit 32 distinct banks

__global__ __launch_bounds__(KT, 8)
void transpose_kernel(float4* __restrict__ out, int npts, int p0)
{
    __shared__ __half2 tile[NLV * TSTR];

    const int b0 = p0 + blockIdx.x * TPP;
    const int t  = threadIdx.x;
    if (b0 >= npts) return;
    const bool full = (b0 + TPP <= npts);
    const bool vec  = full && ((npts & 3) == 0);

    if (vec) {
        #pragma unroll
        for (int idx = t; idx < NLV * (TPP / 4); idx += KT) {
            const int l = idx >> 6;         // / (TPP/4 = 64)
            const int j = idx & 63;
            const uint4 v = __ldcs(reinterpret_cast<const uint4*>(
                &g_scr[(size_t)l * npts + b0 + 4 * j]));
            uint2* dst = reinterpret_cast<uint2*>(&tile[l * TSTR + 4 * j]);
            dst[0] = make_uint2(v.x, v.y);
            dst[1] = make_uint2(v.z, v.w);
        }
    } else {
        for (int idx = t; idx < NLV * TPP; idx += KT) {
            const int l = idx >> 8;
            const int p = idx & (TPP - 1);
            tile[l * TSTR + p] = (b0 + p < npts)
                ? g_scr[(size_t)l * npts + b0 + p]
                : __floats2half2_rn(0.f, 0.f);
        }
    }
    __syncthreads();

    float4* obase = out + (size_t)b0 * 8;
    #pragma unroll
    for (int i = t; i < TPP * 8; i += KT) {
        const int p  = i >> 3;
        const int jp = i & 7;
        if (full || b0 + p < npts) {
            const float2 e0 = __half22float2(tile[(2 * jp)     * TSTR + p]);
            const float2 e1 = __half22float2(tile[(2 * jp + 1) * TSTR + p]);
            __stcs(&obase[i],
                   make_float4(e0.x * SCI, e0.y * SCI, e1.x * SCI, e1.y * SCI));
        }
    }
}

extern "C" void kernel_launch(void* const* d_in, const int* in_sizes, int n_in,
                              void* d_out, int out_size)
{
    const float* x   = (const float*)d_in[0];   // (B, 3) float32
    const float* emb = (const float*)d_in[1];   // (16, 16384, 2) float32
    float4* out      = (float4*)d_out;          // (B, 16, 2) float32

    const int npts = in_sizes[0] / 3;
    // chunk size: ceil over 36 chunks, rounded to 256 for K2 tile alignment
    int ppb = (npts + NCHUNK - 1) / NCHUNK;
    ppb = (ppb + TPP - 1) / TPP * TPP;
    const int smem = 2 * TBL * (int)sizeof(__half2); // 128 KB

    static cudaStream_t s2 = nullptr;
    static cudaEvent_t evK1[GROUPS];
    static cudaEvent_t evDone = nullptr;
    if (!s2) {
        cudaStreamCreateWithFlags(&s2, cudaStreamNonBlocking);
        for (int g = 0; g < GROUPS; g++)
            cudaEventCreateWithFlags(&evK1[g], cudaEventDisableTiming);
        cudaEventCreateWithFlags(&evDone, cudaEventDisableTiming);
        cudaFuncSetAttribute(hashenc_kernel,
                             cudaFuncAttributeMaxDynamicSharedMemorySize, smem);
    }

    for (int g = 0; g < GROUPS; g++) {
        hashenc_kernel<<<dim3(NLV / 2, CPG), BT, smem>>>(
            x, emb, npts, ppb, g * CPG);
        cudaEventRecord(evK1[g], 0);
        cudaStreamWaitEvent(s2, evK1[g], 0);

        const int p0  = g * CPG * ppb;
        const int pts = min(npts - p0, CPG * ppb);
        if (pts > 0) {
            const int tiles = (pts + TPP - 1) / TPP;
            transpose_kernel<<<tiles, KT, 0, s2>>>(out, npts, p0);
        }
    }
    cudaEventRecord(evDone, s2);
    cudaStreamWaitEvent(0, evDone, 0);
}